// round 15
// baseline (speedup 1.0000x reference)
#include <cuda_runtime.h>
#include <cuda_fp16.h>
#include <math.h>
#include <stdint.h>

#define NB 4
#define NS 4000
#define NDIN 1024
#define NDA 512
#define NL 8921
#define SPAD 4096   // padded S
#define LPAD 8960   // padded L (70 * 128)
#define KCH 128     // fp16 K elements per chunk in gemm_z (2 x 64 sub-bufs)
#define STG 65536   // gemm_z stage bytes: A 32K (2 subbufs) + B 32K
#define NSTAGE 3
#define KCM 64      // K per chunk in gemm_sc / gemm_my
#define STGM 49152  // stage bytes: A 16K + B 32K

// ---------------------------------------------------------------------------
// Scratch (device globals: zero-initialized at module load; padded regions are
// never written so they stay zero -> no bounds checks in GEMM operand loads).
// ---------------------------------------------------------------------------
__device__ __half g_xhi[(size_t)NB * NS * NDIN];    // x hi  [b*s][din]
__device__ __half g_Whi[(size_t)NDA * NDIN];        // W hi  [a][din]
__device__ __half g_zhi[(size_t)NB * SPAD * NDA];   // z hi  [b][s][a]
__device__ __half g_zThi[(size_t)NB * NDA * SPAD];  // z^T hi [b][a][s]
__device__ __half g_Uhi[(size_t)LPAD * NDA];
__device__ __half g_ahi[(size_t)NB * LPAD * SPAD];  // e = exp(score), fp16
__device__ float g_sum[(size_t)NB * LPAD];          // per-row sums of e
__device__ float g_inv[(size_t)NB * LPAD];          // 1 / sums

// ---------------------------------------------------------------------------
// Helpers
// ---------------------------------------------------------------------------
__device__ __forceinline__ uint32_t smem_u32(const void* p) {
    uint32_t a;
    asm("{ .reg .u64 t; cvta.to.shared.u64 t, %1; cvt.u32.u64 %0, t; }"
        : "=r"(a) : "l"(p));
    return a;
}
__device__ __forceinline__ void cpa16(uint32_t dst, const void* src) {
    asm volatile("cp.async.cg.shared.global [%0], [%1], 16;"
                 :: "r"(dst), "l"(src) : "memory");
}
#define CP_COMMIT() asm volatile("cp.async.commit_group;" ::: "memory")
#define CP_WAIT(n)  asm volatile("cp.async.wait_group %0;" :: "n"(n) : "memory")

__device__ __forceinline__ void ldsm4(uint32_t& r0, uint32_t& r1,
                                      uint32_t& r2, uint32_t& r3, uint32_t addr) {
    asm volatile("ldmatrix.sync.aligned.m8n8.x4.shared.b16 {%0,%1,%2,%3}, [%4];"
                 : "=r"(r0), "=r"(r1), "=r"(r2), "=r"(r3) : "r"(addr));
}
__device__ __forceinline__ void mma16816(float* d, const uint32_t* a, const uint32_t* b) {
    asm volatile(
        "mma.sync.aligned.m16n8k16.row.col.f32.f16.f16.f32 "
        "{%0,%1,%2,%3}, {%4,%5,%6,%7}, {%8,%9}, {%0,%1,%2,%3};"
        : "+f"(d[0]), "+f"(d[1]), "+f"(d[2]), "+f"(d[3])
        : "r"(a[0]), "r"(a[1]), "r"(a[2]), "r"(a[3]), "r"(b[0]), "r"(b[1]));
}

__device__ __forceinline__ uint32_t pack2h(__half a, __half b) {
    return (uint32_t)__half_as_ushort(a) | ((uint32_t)__half_as_ushort(b) << 16);
}

// Swizzled offset inside a (rows x 64) fp16 sub-buffer (128B rows, 8 x 16B
// groups, group ^= row&7 -> conflict-free cp.async + ldmatrix).
__device__ __forceinline__ uint32_t swoff(int row, int c16) {
    return (uint32_t)(row * 128 + ((c16 ^ (row & 7)) * 16));
}

// ---------------------------------------------------------------------------
// z GEMM: CTA 128x128, 8 warps (2x4), warp tile 64x32, K-chunk 128,
// 3-stage pipeline. Epilogue: fp16 tanh(acc+bias) into padded [b][s][a]
// (rows remapped m -> (b,s)) AND the transposed copy [b][a][s] via an smem
// tile staged in a dead pipeline stage.
// ---------------------------------------------------------------------------
__global__ __launch_bounds__(256, 1)
void gemm_z(const __half* __restrict__ Ahi, const __half* __restrict__ Bhi,
            __half* __restrict__ Ch, __half* __restrict__ Ct,
            const float* __restrict__ bias, int nk)
{
    extern __shared__ char smem[];
    const uint32_t sb = smem_u32(smem);

    const int t = threadIdx.x, w = t >> 5, lane = t & 31;
    const int m0 = blockIdx.y * 128, n0 = blockIdx.x * 128;
    const int wm = (w >> 2) * 64, wn = (w & 3) * 32;

    const __half* Ah = Ahi + (long long)m0 * NDIN;
    const __half* Bh = Bhi + (long long)n0 * NDIN;

    float acc[4][4][4];
#pragma unroll
    for (int i = 0; i < 4; i++)
#pragma unroll
        for (int j = 0; j < 4; j++)
#pragma unroll
            for (int q = 0; q < 4; q++) acc[i][j][q] = 0.f;

    auto load_stage = [&](int c, int s) {
        const uint32_t st = sb + s * STG;
        const int kb = c * KCH;
#pragma unroll
        for (int j = 0; j < 4; j++) {
            const int cid = t + 256 * j;
            const int row = cid >> 3, c16 = cid & 7;
            const uint32_t sw = swoff(row, c16);
#pragma unroll
            for (int sub = 0; sub < 2; sub++) {
                cpa16(st + sub * 16384 + sw,
                      Ah + (long long)row * NDIN + kb + sub * 64 + c16 * 8);
                cpa16(st + 32768 + sub * 16384 + sw,
                      Bh + (long long)row * NDIN + kb + sub * 64 + c16 * 8);
            }
        }
    };

    load_stage(0, 0); CP_COMMIT();
    load_stage(1, 1); CP_COMMIT();

    for (int c = 0; c < nk; c++) {
        const int s = c % NSTAGE;
        if (c == nk - 1) { CP_WAIT(0); } else { CP_WAIT(1); }
        __syncthreads();
        if (c + 2 < nk) { load_stage(c + 2, (c + 2) % NSTAGE); CP_COMMIT(); }

        const int rA = lane & 15, chA = lane >> 4;
        const int r8 = ((lane >> 4) << 3) + (lane & 7);
        const int chB = (lane >> 3) & 1;

#pragma unroll
        for (int kk8 = 0; kk8 < 8; kk8++) {
            const int sub = kk8 >> 2, kkl = kk8 & 3;
            const uint32_t stA = sb + s * STG + sub * 16384;
            const uint32_t stB = sb + s * STG + 32768 + sub * 16384;

            uint32_t bh[4][2];
#pragma unroll
            for (int nh = 0; nh < 2; nh++) {
                const uint32_t off = swoff(wn + nh * 16 + r8, kkl * 2 + chB);
                uint32_t r0, r1, r2, r3;
                ldsm4(r0, r1, r2, r3, stB + off);
                bh[nh * 2][0] = r0; bh[nh * 2][1] = r1;
                bh[nh * 2 + 1][0] = r2; bh[nh * 2 + 1][1] = r3;
            }
            uint32_t ah[4][4];
#pragma unroll
            for (int mt = 0; mt < 4; mt++) {
                const uint32_t off = swoff(wm + mt * 16 + rA, kkl * 2 + chA);
                ldsm4(ah[mt][0], ah[mt][1], ah[mt][2], ah[mt][3], stA + off);
            }
#pragma unroll
            for (int mt = 0; mt < 4; mt++)
#pragma unroll
                for (int nt = 0; nt < 4; nt++)
                    mma16816(acc[mt][nt], ah[mt], bh[nt]);
        }
    }

    // Transpose tile in a stage not read after the final barrier.
    __half* T = (__half*)(smem + (nk % NSTAGE) * STG);   // T[128][132]

#pragma unroll
    for (int mt = 0; mt < 4; mt++) {
        const int r0g = m0 + wm + mt * 16 + (lane >> 2);
        const int r1g = r0g + 8;
        const int b0 = r0g / NS, s0r = r0g - b0 * NS;
        const int b1 = r1g / NS, s1r = r1g - b1 * NS;
        __half* row0 = Ch + ((long long)b0 * SPAD + s0r) * NDA;
        __half* row1 = Ch + ((long long)b1 * SPAD + s1r) * NDA;

#pragma unroll
        for (int nt = 0; nt < 4; nt++) {
            const int cg = n0 + wn + nt * 8 + (lane & 3) * 2;
            const float b0v = bias[cg], b1v = bias[cg + 1];
            const __half h00 = __float2half_rn(tanhf(acc[mt][nt][0] + b0v));
            const __half h01 = __float2half_rn(tanhf(acc[mt][nt][1] + b1v));
            const __half h10 = __float2half_rn(tanhf(acc[mt][nt][2] + b0v));
            const __half h11 = __float2half_rn(tanhf(acc[mt][nt][3] + b1v));
            *(uint32_t*)(row0 + cg) = pack2h(h00, h01);
            *(uint32_t*)(row1 + cg) = pack2h(h10, h11);
            const int cl = cg - n0;
            const int r0l = wm + mt * 16 + (lane >> 2);
            const int r1l = r0l + 8;
            T[(cl + 0) * 132 + r0l] = h00;
            T[(cl + 1) * 132 + r0l] = h01;
            T[(cl + 0) * 132 + r1l] = h10;
            T[(cl + 1) * 132 + r1l] = h11;
        }
    }

    __syncthreads();
#pragma unroll
    for (int it = 0; it < 16; it++) {
        const int i = t + 256 * it;          // 0..4095
        const int al = i >> 5, gsel = i & 31;
        const int mloc = gsel * 4;
        const int m = m0 + mloc;
        const int bb = m / NS, ss = m - bb * NS;
        const __half* p = T + al * 132 + mloc;
        uint2 q;
        q.x = pack2h(p[0], p[1]);
        q.y = pack2h(p[2], p[3]);
        *(uint2*)(Ct + ((long long)bb * NDA + (n0 + al)) * SPAD + ss) = q;
    }
}

// ---------------------------------------------------------------------------
// Scores GEMM: CTA 128(L) x 256(S), 8 warps (2x4), warp tile 64x64 (MMA:LDSM
// ratio 4), K-chunk 64, 3-stage pipeline.
// Epilogue: e = exp(score) fp16 (pad s-cols -> 0) + per-row exp-sum atomics.
// ---------------------------------------------------------------------------
__global__ __launch_bounds__(256, 1)
void gemm_sc(const __half* __restrict__ Ahi, const __half* __restrict__ Bhi,
             __half* __restrict__ Ch, float* __restrict__ rowsum, int nk)
{
    extern __shared__ char smem[];
    const uint32_t sb = smem_u32(smem);

    const int t = threadIdx.x, w = t >> 5, lane = t & 31;
    const int m0 = blockIdx.y * 128, n0 = blockIdx.x * 256, b = blockIdx.z;
    const int wm = (w >> 2) * 64, wn = (w & 3) * 64;

    const __half* Ah = Ahi + (long long)m0 * NDA;
    const __half* Bh = Bhi + (long long)b * SPAD * NDA + (long long)n0 * NDA;

    float acc[4][8][4];
#pragma unroll
    for (int i = 0; i < 4; i++)
#pragma unroll
        for (int j = 0; j < 8; j++)
#pragma unroll
            for (int q = 0; q < 4; q++) acc[i][j][q] = 0.f;

    // stage: A 128x64 @0 (16KB), B 256x64 @16384 (32KB)
    auto load_stage = [&](int c, int s) {
        const uint32_t st = sb + s * STGM;
        const int kb = c * KCM;
#pragma unroll
        for (int j = 0; j < 4; j++) {
            const int cid = t + 256 * j;
            const int row = cid >> 3, c16 = cid & 7;
            cpa16(st + swoff(row, c16), Ah + (long long)row * NDA + kb + c16 * 8);
        }
#pragma unroll
        for (int j = 0; j < 8; j++) {
            const int cid = t + 256 * j;
            const int row = cid >> 3, c16 = cid & 7;
            cpa16(st + 16384 + swoff(row, c16), Bh + (long long)row * NDA + kb + c16 * 8);
        }
    };

    load_stage(0, 0); CP_COMMIT();
    load_stage(1, 1); CP_COMMIT();

    for (int c = 0; c < nk; c++) {
        const int s = c % NSTAGE;
        if (c == nk - 1) { CP_WAIT(0); } else { CP_WAIT(1); }
        __syncthreads();
        if (c + 2 < nk) { load_stage(c + 2, (c + 2) % NSTAGE); CP_COMMIT(); }

        const uint32_t stA = sb + s * STGM;
        const uint32_t stB = stA + 16384;
        const int rA = lane & 15, chA = lane >> 4;
        const int r8 = ((lane >> 4) << 3) + (lane & 7);
        const int chB = (lane >> 3) & 1;

#pragma unroll
        for (int kkl = 0; kkl < 4; kkl++) {
            uint32_t bh[8][2];
#pragma unroll
            for (int nh = 0; nh < 4; nh++) {
                const uint32_t off = swoff(wn + nh * 16 + r8, kkl * 2 + chB);
                uint32_t r0, r1, r2, r3;
                ldsm4(r0, r1, r2, r3, stB + off);
                bh[nh * 2][0] = r0; bh[nh * 2][1] = r1;
                bh[nh * 2 + 1][0] = r2; bh[nh * 2 + 1][1] = r3;
            }
            uint32_t ah[4][4];
#pragma unroll
            for (int mt = 0; mt < 4; mt++) {
                const uint32_t off = swoff(wm + mt * 16 + rA, kkl * 2 + chA);
                ldsm4(ah[mt][0], ah[mt][1], ah[mt][2], ah[mt][3], stA + off);
            }
#pragma unroll
            for (int mt = 0; mt < 4; mt++)
#pragma unroll
                for (int nt = 0; nt < 8; nt++)
                    mma16816(acc[mt][nt], ah[mt], bh[nt]);
        }
    }

    // Epilogue: e = exp(score), fp16 stores, row-sum atomics.
    __half* Cb = Ch + (long long)b * LPAD * SPAD;
#pragma unroll
    for (int mt = 0; mt < 4; mt++) {
        const int r0g = m0 + wm + mt * 16 + (lane >> 2);
        const int r1g = r0g + 8;
        __half* row0 = Cb + (long long)r0g * SPAD;
        __half* row1 = Cb + (long long)r1g * SPAD;
        float p0 = 0.f, p1 = 0.f;
#pragma unroll
        for (int nt = 0; nt < 8; nt++) {
            const int cg = n0 + wn + nt * 8 + (lane & 3) * 2;
            const bool ok = (cg < NS);           // 4000 even -> pair-safe
            float e0 = 0.f, e1 = 0.f, e2 = 0.f, e3 = 0.f;
            if (ok) {
                e0 = __expf(acc[mt][nt][0]); e1 = __expf(acc[mt][nt][1]);
                e2 = __expf(acc[mt][nt][2]); e3 = __expf(acc[mt][nt][3]);
            }
            *(uint32_t*)(row0 + cg) = pack2h(__float2half_rn(e0), __float2half_rn(e1));
            *(uint32_t*)(row1 + cg) = pack2h(__float2half_rn(e2), __float2half_rn(e3));
            p0 += e0 + e1;
            p1 += e2 + e3;
        }
        p0 += __shfl_xor_sync(0xffffffffu, p0, 1);
        p0 += __shfl_xor_sync(0xffffffffu, p0, 2);
        p1 += __shfl_xor_sync(0xffffffffu, p1, 1);
        p1 += __shfl_xor_sync(0xffffffffu, p1, 2);
        if ((lane & 3) == 0) {
            atomicAdd(&rowsum[(long long)b * LPAD + r0g], p0);
            atomicAdd(&rowsum[(long long)b * LPAD + r1g], p1);
        }
    }
}

// ---------------------------------------------------------------------------
// Fused m+y GEMM: CTA 128(L) x 256(D_A), warp 64x64, K-chunk 64, 3-stage.
// Reads unnormalized e; y partials scaled by inv_sum[row]. Alpha emission
// balanced across the two n-tiles by K-chunk.
// ---------------------------------------------------------------------------
__global__ __launch_bounds__(256, 1)
void gemm_my(const __half* __restrict__ Ahi, const __half* __restrict__ Bhi,
             const float* __restrict__ Vw, const float* __restrict__ inv,
             float* __restrict__ yout, float* __restrict__ alpha,
             int nk, int Mvalid, int ldA, int ldB,
             long long sA, long long sB)
{
    extern __shared__ char smem[];
    const uint32_t sb = smem_u32(smem);

    const int t = threadIdx.x, w = t >> 5, lane = t & 31;
    const int m0 = blockIdx.y * 128, n0 = blockIdx.x * 256, b = blockIdx.z;
    const int wm = (w >> 2) * 64, wn = (w & 3) * 64;

    const __half* Ah = Ahi + b * sA + (long long)m0 * ldA;
    const __half* Bh = Bhi + b * sB + (long long)n0 * ldB;

    float acc[4][8][4];
#pragma unroll
    for (int i = 0; i < 4; i++)
#pragma unroll
        for (int j = 0; j < 8; j++)
#pragma unroll
            for (int q = 0; q < 4; q++) acc[i][j][q] = 0.f;

    auto load_stage = [&](int c, int s) {
        const uint32_t st = sb + s * STGM;
        const int kb = c * KCM;
#pragma unroll
        for (int j = 0; j < 4; j++) {
            const int cid = t + 256 * j;
            const int row = cid >> 3, c16 = cid & 7;
            cpa16(st + swoff(row, c16), Ah + (long long)row * ldA + kb + c16 * 8);
        }
#pragma unroll
        for (int j = 0; j < 8; j++) {
            const int cid = t + 256 * j;
            const int row = cid >> 3, c16 = cid & 7;
            cpa16(st + 16384 + swoff(row, c16), Bh + (long long)row * ldB + kb + c16 * 8);
        }
    };

    load_stage(0, 0); CP_COMMIT();
    load_stage(1, 1); CP_COMMIT();

    for (int c = 0; c < nk; c++) {
        const int s = c % NSTAGE;
        if (c == nk - 1) { CP_WAIT(0); } else { CP_WAIT(1); }
        __syncthreads();
        if (c + 2 < nk) { load_stage(c + 2, (c + 2) % NSTAGE); CP_COMMIT(); }

        const uint32_t stA = sb + s * STGM;
        const uint32_t stB = stA + 16384;
        const int rA = lane & 15, chA = lane >> 4;
        const int r8 = ((lane >> 4) << 3) + (lane & 7);
        const int chB = (lane >> 3) & 1;

#pragma unroll
        for (int kkl = 0; kkl < 4; kkl++) {
            uint32_t bh[8][2];
#pragma unroll
            for (int nh = 0; nh < 4; nh++) {
                const uint32_t off = swoff(wn + nh * 16 + r8, kkl * 2 + chB);
                uint32_t r0, r1, r2, r3;
                ldsm4(r0, r1, r2, r3, stB + off);
                bh[nh * 2][0] = r0; bh[nh * 2][1] = r1;
                bh[nh * 2 + 1][0] = r2; bh[nh * 2 + 1][1] = r3;
            }
            uint32_t ah[4][4];
#pragma unroll
            for (int mt = 0; mt < 4; mt++) {
                const uint32_t off = swoff(wm + mt * 16 + rA, kkl * 2 + chA);
                ldsm4(ah[mt][0], ah[mt][1], ah[mt][2], ah[mt][3], stA + off);
            }
#pragma unroll
            for (int mt = 0; mt < 4; mt++)
#pragma unroll
                for (int nt = 0; nt < 8; nt++)
                    mma16816(acc[mt][nt], ah[mt], bh[nt]);
        }

        // Fused alpha emission (balanced: each n-tile handles half the chunks)
        if ((c >> 5) == (int)blockIdx.x) {
            const int kb = c * KCM;
#pragma unroll
            for (int j = 0; j < 8; j++) {
                const int g = t + 256 * j;        // 0..2047
                const int row = g >> 4, c4 = g & 15;
                const int col = kb + c4 * 4;      // NS%4==0 -> group all-or-none
                const int lrow = m0 + row;
                if (col < NS && lrow < Mvalid) {
                    const uint32_t addr = stA + swoff(row, c4 >> 1) + (c4 & 1) * 8;
                    uint32_t q0, q1;
                    asm volatile("ld.shared.v2.u32 {%0,%1}, [%2];"
                                 : "=r"(q0), "=r"(q1) : "r"(addr));
                    __half2 h01 = *reinterpret_cast<__half2*>(&q0);
                    __half2 h23 = *reinterpret_cast<__half2*>(&q1);
                    const float iv = inv[(long long)b * LPAD + lrow];
                    float2 f01 = __half22float2(h01), f23 = __half22float2(h23);
                    float4 v = make_float4(f01.x * iv, f01.y * iv,
                                           f23.x * iv, f23.y * iv);
                    *(float4*)(alpha + ((long long)b * NL + lrow) * NS + col) = v;
                }
            }
        }
    }

    // Fused y epilogue: partial dot with Vw rows, scale by inv, atomicAdd.
#pragma unroll
    for (int mt = 0; mt < 4; mt++) {
        const int r0g = m0 + wm + mt * 16 + (lane >> 2);
        const int r1g = r0g + 8;
        float p0 = 0.f, p1 = 0.f;
#pragma unroll
        for (int nt = 0; nt < 8; nt++) {
            const int cg = n0 + wn + nt * 8 + (lane & 3) * 2;
            if (r0g < Mvalid) {
                const float2 vv = *(const float2*)(Vw + (long long)r0g * NDA + cg);
                p0 += acc[mt][nt][0] * vv.x + acc[mt][nt][1] * vv.y;
            }
            if (r1g < Mvalid) {
                const float2 vv = *(const float2*)(Vw + (long long)r1g * NDA + cg);
                p1 += acc[mt][nt][2] * vv.x + acc[mt][nt][3] * vv.y;
            }
        }
        p0 += __shfl_xor_sync(0xffffffffu, p0, 1);
        p0 += __shfl_xor_sync(0xffffffffu, p0, 2);
        p1 += __shfl_xor_sync(0xffffffffu, p1, 1);
        p1 += __shfl_xor_sync(0xffffffffu, p1, 2);
        if ((lane & 3) == 0) {
            if (r0g < Mvalid)
                atomicAdd(&yout[(long long)b * NL + r0g],
                          p0 * inv[(long long)b * LPAD + r0g]);
            if (r1g < Mvalid)
                atomicAdd(&yout[(long long)b * NL + r1g],
                          p1 * inv[(long long)b * LPAD + r1g]);
        }
    }
}

// ---------------------------------------------------------------------------
// fp32 -> fp16 flat converter; optionally zeroes an aux float array.
// ---------------------------------------------------------------------------
__global__ __launch_bounds__(256)
void split_hi(const float* __restrict__ src, __half* __restrict__ dhi,
              long long n, float* __restrict__ aux, int naux)
{
    const int gid = blockIdx.x * 256 + threadIdx.x;
    if (aux && gid < naux) aux[gid] = 0.f;
    const long long i = (long long)gid * 4;
    if (i >= n) return;
    float4 v = *(const float4*)(src + i);
    uint2 ph;
    ph.x = pack2h(__float2half_rn(v.x), __float2half_rn(v.y));
    ph.y = pack2h(__float2half_rn(v.z), __float2half_rn(v.w));
    *(uint2*)(dhi + i) = ph;
}

// ---------------------------------------------------------------------------
// inv = 1/sum  AND  y init (y[b,l] = V_b[l]) in one launch
// ---------------------------------------------------------------------------
__global__ __launch_bounds__(256)
void inv_y_kernel(const float* __restrict__ s, float* __restrict__ inv,
                  const float* __restrict__ Vb, float* __restrict__ y)
{
    const int i = blockIdx.x * 256 + threadIdx.x;
    if (i < NB * LPAD) {
        const float v = s[i];
        inv[i] = (v > 0.f) ? (1.f / v) : 0.f;
        const int b = i / LPAD, l = i - b * LPAD;
        if (l < NL) y[b * NL + l] = Vb[l];
    }
}

// ---------------------------------------------------------------------------
extern "C" void kernel_launch(void* const* d_in, const int* in_sizes, int n_in,
                              void* d_out, int out_size)
{
    const float* x  = (const float*)d_in[0];
    const float* Ww = (const float*)d_in[1];
    const float* Wb = (const float*)d_in[2];
    const float* Uw = (const float*)d_in[3];
    const float* Vw = (const float*)d_in[4];
    const float* Vb = (const float*)d_in[5];

    float* y     = (float*)d_out;
    float* alpha = (float*)d_out + (size_t)NB * NL;

    float *sums, *invs;
    __half *xhi, *whi, *zhi, *zThi, *uhi, *ahi;
    cudaGetSymbolAddress((void**)&sums, g_sum);
    cudaGetSymbolAddress((void**)&invs, g_inv);
    cudaGetSymbolAddress((void**)&xhi, g_xhi);
    cudaGetSymbolAddress((void**)&whi, g_Whi);
    cudaGetSymbolAddress((void**)&zhi, g_zhi);
    cudaGetSymbolAddress((void**)&zThi, g_zThi);
    cudaGetSymbolAddress((void**)&uhi, g_Uhi);
    cudaGetSymbolAddress((void**)&ahi, g_ahi);

    cudaFuncSetAttribute((const void*)gemm_z,
                         cudaFuncAttributeMaxDynamicSharedMemorySize, NSTAGE * STG);
    cudaFuncSetAttribute((const void*)gemm_sc,
                         cudaFuncAttributeMaxDynamicSharedMemorySize, NSTAGE * STGM);
    cudaFuncSetAttribute((const void*)gemm_my,
                         cudaFuncAttributeMaxDynamicSharedMemorySize, NSTAGE * STGM);

    // 1) convert x, W, U to fp16 (U launch also zeroes the row-sum scratch)
    {
        long long nx = (long long)NB * NS * NDIN;
        split_hi<<<(unsigned)((nx / 4 + 255) / 256), 256>>>(x, xhi, nx, nullptr, 0);
        long long nw = (long long)NDA * NDIN;
        split_hi<<<(unsigned)((nw / 4 + 255) / 256), 256>>>(Ww, whi, nw, nullptr, 0);
        long long nu = (long long)NL * NDA;
        split_hi<<<(unsigned)((nu / 4 + 255) / 256), 256>>>(Uw, uhi, nu, sums, NB * LPAD);
    }
    // 2) z = tanh(x @ W^T + b) -> fp16 zhi ([b][s][a]) AND zThi ([b][a][s])
    {
        dim3 g(NDA / 128, (NB * NS) / 128, 1);
        gemm_z<<<g, 256, NSTAGE * STG>>>(xhi, whi, zhi, zThi, Wb, NDIN / KCH);
    }
    // 3) e = exp(U @ z^T) -> fp16 g_ahi (pad s-cols -> 0) + row sums
    //    CTA 128x256, warp 64x64 (MMA:LDSM ratio 4)
    {
        dim3 g(SPAD / 256, LPAD / 128, NB);
        gemm_sc<<<g, 256, NSTAGE * STGM>>>(uhi, zhi, ahi, sums, NDA / KCM);
    }
    // 4) inv = 1/sum; y = V_b (one launch)
    inv_y_kernel<<<(NB * LPAD + 255) / 256, 256>>>(sums, invs, Vb, y);

    // 5) fused m/y/alpha: y[b,l] += inv * sum_a (e@z)[b,l,a] * V[l,a];
    //    alpha = e*inv streamed from smem e tiles, balanced across n-tiles.
    {
        dim3 g(NDA / 256, LPAD / 128, NB);
        gemm_my<<<g, 256, NSTAGE * STGM>>>(
            ahi, zThi, Vw, invs, y, alpha,
            63, NL, SPAD, SPAD,
            (long long)LPAD * SPAD, (long long)NDA * SPAD);
    }
}

// round 16
// speedup vs baseline: 1.0103x; 1.0103x over previous
#include <cuda_runtime.h>
#include <cuda_fp16.h>
#include <math.h>
#include <stdint.h>

#define NB 4
#define NS 4000
#define NDIN 1024
#define NDA 512
#define NL 8921
#define SPAD 4096   // padded S
#define LPAD 8960   // padded L (70 * 128)
#define KCH 128     // fp16 K elements per chunk in gemm_mma (2 x 64 sub-bufs)
#define STG 65536   // gemm_mma stage bytes: A 32K (2 subbufs) + B 32K
#define NSTAGE 3
#define KCM 64      // K per chunk in gemm_my
#define STGM 49152  // gemm_my stage bytes: A 16K + B 32K

// ---------------------------------------------------------------------------
// Scratch (device globals: zero-initialized at module load; padded regions are
// never written so they stay zero -> no bounds checks in GEMM operand loads).
// ---------------------------------------------------------------------------
__device__ __half g_xhi[(size_t)NB * NS * NDIN];    // x hi  [b*s][din]
__device__ __half g_Whi[(size_t)NDA * NDIN];        // W hi  [a][din]
__device__ __half g_zhi[(size_t)NB * SPAD * NDA];   // z hi  [b][s][a]
__device__ __half g_zThi[(size_t)NB * NDA * SPAD];  // z^T hi [b][a][s]
__device__ __half g_Uhi[(size_t)LPAD * NDA];
__device__ __half g_ahi[(size_t)NB * LPAD * SPAD];  // e = exp(score), fp16
__device__ float g_sum[(size_t)NB * LPAD];          // per-row sums of e
__device__ float g_inv[(size_t)NB * LPAD];          // 1 / sums

// ---------------------------------------------------------------------------
// Helpers
// ---------------------------------------------------------------------------
__device__ __forceinline__ uint32_t smem_u32(const void* p) {
    uint32_t a;
    asm("{ .reg .u64 t; cvta.to.shared.u64 t, %1; cvt.u32.u64 %0, t; }"
        : "=r"(a) : "l"(p));
    return a;
}
__device__ __forceinline__ void cpa16(uint32_t dst, const void* src) {
    asm volatile("cp.async.cg.shared.global [%0], [%1], 16;"
                 :: "r"(dst), "l"(src) : "memory");
}
#define CP_COMMIT() asm volatile("cp.async.commit_group;" ::: "memory")
#define CP_WAIT(n)  asm volatile("cp.async.wait_group %0;" :: "n"(n) : "memory")

__device__ __forceinline__ void ldsm4(uint32_t& r0, uint32_t& r1,
                                      uint32_t& r2, uint32_t& r3, uint32_t addr) {
    asm volatile("ldmatrix.sync.aligned.m8n8.x4.shared.b16 {%0,%1,%2,%3}, [%4];"
                 : "=r"(r0), "=r"(r1), "=r"(r2), "=r"(r3) : "r"(addr));
}
__device__ __forceinline__ void mma16816(float* d, const uint32_t* a, const uint32_t* b) {
    asm volatile(
        "mma.sync.aligned.m16n8k16.row.col.f32.f16.f16.f32 "
        "{%0,%1,%2,%3}, {%4,%5,%6,%7}, {%8,%9}, {%0,%1,%2,%3};"
        : "+f"(d[0]), "+f"(d[1]), "+f"(d[2]), "+f"(d[3])
        : "r"(a[0]), "r"(a[1]), "r"(a[2]), "r"(a[3]), "r"(b[0]), "r"(b[1]));
}

__device__ __forceinline__ uint32_t pack2h(__half a, __half b) {
    return (uint32_t)__half_as_ushort(a) | ((uint32_t)__half_as_ushort(b) << 16);
}

// Fast tanh via MUFU.EX2: tanh(v) = 1 - 2/(e^{2v}+1). Rel err ~2^-22,
// fully absorbed by the subsequent fp16 rounding (2^-12).
__device__ __forceinline__ float ftanh(float v) {
    const float e = __expf(2.f * v);
    return 1.f - __fdividef(2.f, e + 1.f);
}

// Swizzled offset inside a (rows x 64) fp16 sub-buffer (128B rows, 8 x 16B
// groups, group ^= row&7 -> conflict-free cp.async + ldmatrix).
__device__ __forceinline__ uint32_t swoff(int row, int c16) {
    return (uint32_t)(row * 128 + ((c16 ^ (row & 7)) * 16));
}

// ---------------------------------------------------------------------------
// fp16 single-pass GEMM, CTA 128x128, 8 warps (2x4), warp tile 64x32,
// K-chunk 128 (2x64 sub-bufs), 3-stage cp.async pipeline.
// EXPSUM=false (z path): Ch(fp16, padded [b][s][a]) = tanh(acc + bias[n]),
//   rows remapped m -> (b,s); ALSO emits the transposed copy Ct ([b][a][s])
//   via an smem tile staged in a dead pipeline stage (coalesced stores).
// EXPSUM=true (scores): Ch(fp16) = exp(acc) for n < Nvalid else 0; atomicAdd
//   per-row partial exp-sums into rowsum (max-free softmax; |logit| < ~6).
// ---------------------------------------------------------------------------
template <bool EXPSUM>
__global__ __launch_bounds__(256, 1)
void gemm_mma(const __half* __restrict__ Ahi, const __half* __restrict__ Bhi,
              __half* __restrict__ Ch, __half* __restrict__ Ct,
              const float* __restrict__ bias, float* __restrict__ rowsum,
              int nk, int Nvalid, int ldA, int ldB, int ldC,
              long long sA, long long sB, long long sC)
{
    extern __shared__ char smem[];
    const uint32_t sb = smem_u32(smem);

    const int t = threadIdx.x, w = t >> 5, lane = t & 31;
    const int m0 = blockIdx.y * 128, n0 = blockIdx.x * 128, b = blockIdx.z;
    const int wm = (w >> 2) * 64, wn = (w & 3) * 32;

    const __half* Ah = Ahi + b * sA + (long long)m0 * ldA;
    const __half* Bh = Bhi + b * sB + (long long)n0 * ldB;

    float acc[4][4][4];
#pragma unroll
    for (int i = 0; i < 4; i++)
#pragma unroll
        for (int j = 0; j < 4; j++)
#pragma unroll
            for (int q = 0; q < 4; q++) acc[i][j][q] = 0.f;

    auto load_stage = [&](int c, int s) {
        const uint32_t st = sb + s * STG;
        const int kb = c * KCH;
#pragma unroll
        for (int j = 0; j < 4; j++) {
            const int cid = t + 256 * j;
            const int row = cid >> 3, c16 = cid & 7;
            const uint32_t sw = swoff(row, c16);
#pragma unroll
            for (int sub = 0; sub < 2; sub++) {
                cpa16(st + sub * 16384 + sw,
                      Ah + (long long)row * ldA + kb + sub * 64 + c16 * 8);
                cpa16(st + 32768 + sub * 16384 + sw,
                      Bh + (long long)row * ldB + kb + sub * 64 + c16 * 8);
            }
        }
    };

    load_stage(0, 0); CP_COMMIT();
    load_stage(1, 1); CP_COMMIT();

    for (int c = 0; c < nk; c++) {
        const int s = c % NSTAGE;
        if (c == nk - 1) { CP_WAIT(0); } else { CP_WAIT(1); }
        __syncthreads();
        if (c + 2 < nk) { load_stage(c + 2, (c + 2) % NSTAGE); CP_COMMIT(); }

        const int rA = lane & 15, chA = lane >> 4;
        const int r8 = ((lane >> 4) << 3) + (lane & 7);
        const int chB = (lane >> 3) & 1;

#pragma unroll
        for (int kk8 = 0; kk8 < 8; kk8++) {
            const int sub = kk8 >> 2, kkl = kk8 & 3;
            const uint32_t stA = sb + s * STG + sub * 16384;
            const uint32_t stB = sb + s * STG + 32768 + sub * 16384;

            uint32_t bh[4][2];
#pragma unroll
            for (int nh = 0; nh < 2; nh++) {
                const uint32_t off = swoff(wn + nh * 16 + r8, kkl * 2 + chB);
                uint32_t r0, r1, r2, r3;
                ldsm4(r0, r1, r2, r3, stB + off);
                bh[nh * 2][0] = r0; bh[nh * 2][1] = r1;
                bh[nh * 2 + 1][0] = r2; bh[nh * 2 + 1][1] = r3;
            }
            uint32_t ah[4][4];
#pragma unroll
            for (int mt = 0; mt < 4; mt++) {
                const uint32_t off = swoff(wm + mt * 16 + rA, kkl * 2 + chA);
                ldsm4(ah[mt][0], ah[mt][1], ah[mt][2], ah[mt][3], stA + off);
            }
#pragma unroll
            for (int mt = 0; mt < 4; mt++)
#pragma unroll
                for (int nt = 0; nt < 4; nt++)
                    mma16816(acc[mt][nt], ah[mt], bh[nt]);
        }
    }

    // Transpose tile lives in a stage not read after the final barrier:
    // only stage (nk-1)%3 is read post-loop, so stage nk%3 is free.
    __half* T = (__half*)(smem + (nk % NSTAGE) * STG);   // T[128][132]

#pragma unroll
    for (int mt = 0; mt < 4; mt++) {
        const int r0g = m0 + wm + mt * 16 + (lane >> 2);
        const int r1g = r0g + 8;
        float p0 = 0.f, p1 = 0.f;

        __half *row0, *row1;
        if (EXPSUM) {
            __half* Cb = Ch + b * sC;
            row0 = Cb + (long long)r0g * ldC;
            row1 = Cb + (long long)r1g * ldC;
        } else {
            // z path: remap m -> (batch, seq) into padded [b][s][a] buffer
            const int b0 = r0g / NS, s0r = r0g - b0 * NS;
            const int b1 = r1g / NS, s1r = r1g - b1 * NS;
            row0 = Ch + ((long long)b0 * SPAD + s0r) * ldC;
            row1 = Ch + ((long long)b1 * SPAD + s1r) * ldC;
        }

#pragma unroll
        for (int nt = 0; nt < 4; nt++) {
            const int cg = n0 + wn + nt * 8 + (lane & 3) * 2;
            if (EXPSUM) {
                const bool ok = (cg < Nvalid);   // 4000 even -> pair-safe
                float e0 = 0.f, e1 = 0.f, e2 = 0.f, e3 = 0.f;
                if (ok) {
                    e0 = __expf(acc[mt][nt][0]); e1 = __expf(acc[mt][nt][1]);
                    e2 = __expf(acc[mt][nt][2]); e3 = __expf(acc[mt][nt][3]);
                }
                *(uint32_t*)(row0 + cg) = pack2h(__float2half_rn(e0), __float2half_rn(e1));
                *(uint32_t*)(row1 + cg) = pack2h(__float2half_rn(e2), __float2half_rn(e3));
                p0 += e0 + e1;
                p1 += e2 + e3;
            } else {
                const float b0v = bias[cg], b1v = bias[cg + 1];
                const __half h00 = __float2half_rn(ftanh(acc[mt][nt][0] + b0v));
                const __half h01 = __float2half_rn(ftanh(acc[mt][nt][1] + b1v));
                const __half h10 = __float2half_rn(ftanh(acc[mt][nt][2] + b0v));
                const __half h11 = __float2half_rn(ftanh(acc[mt][nt][3] + b1v));
                *(uint32_t*)(row0 + cg) = pack2h(h00, h01);
                *(uint32_t*)(row1 + cg) = pack2h(h10, h11);
                // stage into transpose tile: T[a_local][m_local]
                const int cl = cg - n0;
                const int r0l = wm + mt * 16 + (lane >> 2);
                const int r1l = r0l + 8;
                T[(cl + 0) * 132 + r0l] = h00;
                T[(cl + 1) * 132 + r0l] = h01;
                T[(cl + 0) * 132 + r1l] = h10;
                T[(cl + 1) * 132 + r1l] = h11;
            }
        }
        if (EXPSUM) {
            p0 += __shfl_xor_sync(0xffffffffu, p0, 1);
            p0 += __shfl_xor_sync(0xffffffffu, p0, 2);
            p1 += __shfl_xor_sync(0xffffffffu, p1, 1);
            p1 += __shfl_xor_sync(0xffffffffu, p1, 2);
            if ((lane & 3) == 0) {
                atomicAdd(&rowsum[(long long)b * LPAD + r0g], p0);
                atomicAdd(&rowsum[(long long)b * LPAD + r1g], p1);
            }
        }
    }

    if (!EXPSUM) {
        __syncthreads();
        // Coalesced transposed store: zThi[b][a][s]. 4-half groups never
        // straddle a batch boundary (NS % 4 == 0).
#pragma unroll
        for (int it = 0; it < 16; it++) {
            const int i = t + 256 * it;          // 0..4095
            const int al = i >> 5, gsel = i & 31;
            const int mloc = gsel * 4;
            const int m = m0 + mloc;
            const int bb = m / NS, ss = m - bb * NS;
            const __half* p = T + al * 132 + mloc;
            uint2 q;
            q.x = pack2h(p[0], p[1]);
            q.y = pack2h(p[2], p[3]);
            *(uint2*)(Ct + ((long long)bb * NDA + (n0 + al)) * SPAD + ss) = q;
        }
    }
}

// ---------------------------------------------------------------------------
// Fused m+y GEMM: CTA 128(L) x 256(D_A), 8 warps (2x4), warp tile 64x64,
// K-chunk 64, 3-stage pipeline. Reads unnormalized e; y partials scaled by
// inv_sum[row]. Alpha emission (alpha = e*inv, fp32 to d_out) is balanced
// across the two n-tiles by K-chunk: tile 0 emits chunks [0,32), tile 1
// emits chunks [32,63).
// ---------------------------------------------------------------------------
__global__ __launch_bounds__(256, 1)
void gemm_my(const __half* __restrict__ Ahi, const __half* __restrict__ Bhi,
             const float* __restrict__ Vw, const float* __restrict__ inv,
             float* __restrict__ yout, float* __restrict__ alpha,
             int nk, int Mvalid, int ldA, int ldB,
             long long sA, long long sB)
{
    extern __shared__ char smem[];
    const uint32_t sb = smem_u32(smem);

    const int t = threadIdx.x, w = t >> 5, lane = t & 31;
    const int m0 = blockIdx.y * 128, n0 = blockIdx.x * 256, b = blockIdx.z;
    const int wm = (w >> 2) * 64, wn = (w & 3) * 64;

    const __half* Ah = Ahi + b * sA + (long long)m0 * ldA;
    const __half* Bh = Bhi + b * sB + (long long)n0 * ldB;

    float acc[4][8][4];
#pragma unroll
    for (int i = 0; i < 4; i++)
#pragma unroll
        for (int j = 0; j < 8; j++)
#pragma unroll
            for (int q = 0; q < 4; q++) acc[i][j][q] = 0.f;

    // stage: A 128x64 @0 (16KB), B 256x64 @16384 (32KB)
    auto load_stage = [&](int c, int s) {
        const uint32_t st = sb + s * STGM;
        const int kb = c * KCM;
#pragma unroll
        for (int j = 0; j < 4; j++) {
            const int cid = t + 256 * j;
            const int row = cid >> 3, c16 = cid & 7;
            cpa16(st + swoff(row, c16), Ah + (long long)row * ldA + kb + c16 * 8);
        }
#pragma unroll
        for (int j = 0; j < 8; j++) {
            const int cid = t + 256 * j;
            const int row = cid >> 3, c16 = cid & 7;
            cpa16(st + 16384 + swoff(row, c16), Bh + (long long)row * ldB + kb + c16 * 8);
        }
    };

    load_stage(0, 0); CP_COMMIT();
    load_stage(1, 1); CP_COMMIT();

    for (int c = 0; c < nk; c++) {
        const int s = c % NSTAGE;
        if (c == nk - 1) { CP_WAIT(0); } else { CP_WAIT(1); }
        __syncthreads();
        if (c + 2 < nk) { load_stage(c + 2, (c + 2) % NSTAGE); CP_COMMIT(); }

        const uint32_t stA = sb + s * STGM;
        const uint32_t stB = stA + 16384;
        const int rA = lane & 15, chA = lane >> 4;
        const int r8 = ((lane >> 4) << 3) + (lane & 7);
        const int chB = (lane >> 3) & 1;

#pragma unroll
        for (int kkl = 0; kkl < 4; kkl++) {
            uint32_t bh[8][2];
#pragma unroll
            for (int nh = 0; nh < 4; nh++) {
                const uint32_t off = swoff(wn + nh * 16 + r8, kkl * 2 + chB);
                uint32_t r0, r1, r2, r3;
                ldsm4(r0, r1, r2, r3, stB + off);
                bh[nh * 2][0] = r0; bh[nh * 2][1] = r1;
                bh[nh * 2 + 1][0] = r2; bh[nh * 2 + 1][1] = r3;
            }
            uint32_t ah[4][4];
#pragma unroll
            for (int mt = 0; mt < 4; mt++) {
                const uint32_t off = swoff(wm + mt * 16 + rA, kkl * 2 + chA);
                ldsm4(ah[mt][0], ah[mt][1], ah[mt][2], ah[mt][3], stA + off);
            }
#pragma unroll
            for (int mt = 0; mt < 4; mt++)
#pragma unroll
                for (int nt = 0; nt < 8; nt++)
                    mma16816(acc[mt][nt], ah[mt], bh[nt]);
        }

        // Fused alpha emission (balanced: each n-tile handles half the chunks)
        if ((c >> 5) == (int)blockIdx.x) {
            const int kb = c * KCM;
#pragma unroll
            for (int j = 0; j < 8; j++) {
                const int g = t + 256 * j;        // 0..2047
                const int row = g >> 4, c4 = g & 15;
                const int col = kb + c4 * 4;      // NS%4==0 -> group all-or-none
                const int lrow = m0 + row;
                if (col < NS && lrow < Mvalid) {
                    const uint32_t addr = stA + swoff(row, c4 >> 1) + (c4 & 1) * 8;
                    uint32_t q0, q1;
                    asm volatile("ld.shared.v2.u32 {%0,%1}, [%2];"
                                 : "=r"(q0), "=r"(q1) : "r"(addr));
                    __half2 h01 = *reinterpret_cast<__half2*>(&q0);
                    __half2 h23 = *reinterpret_cast<__half2*>(&q1);
                    const float iv = inv[(long long)b * LPAD + lrow];
                    float2 f01 = __half22float2(h01), f23 = __half22float2(h23);
                    float4 v = make_float4(f01.x * iv, f01.y * iv,
                                           f23.x * iv, f23.y * iv);
                    *(float4*)(alpha + ((long long)b * NL + lrow) * NS + col) = v;
                }
            }
        }
    }

    // Fused y epilogue: partial dot with Vw rows, scale by inv, atomicAdd.
#pragma unroll
    for (int mt = 0; mt < 4; mt++) {
        const int r0g = m0 + wm + mt * 16 + (lane >> 2);
        const int r1g = r0g + 8;
        float p0 = 0.f, p1 = 0.f;
#pragma unroll
        for (int nt = 0; nt < 8; nt++) {
            const int cg = n0 + wn + nt * 8 + (lane & 3) * 2;
            if (r0g < Mvalid) {
                const float2 vv = *(const float2*)(Vw + (long long)r0g * NDA + cg);
                p0 += acc[mt][nt][0] * vv.x + acc[mt][nt][1] * vv.y;
            }
            if (r1g < Mvalid) {
                const float2 vv = *(const float2*)(Vw + (long long)r1g * NDA + cg);
                p1 += acc[mt][nt][2] * vv.x + acc[mt][nt][3] * vv.y;
            }
        }
        p0 += __shfl_xor_sync(0xffffffffu, p0, 1);
        p0 += __shfl_xor_sync(0xffffffffu, p0, 2);
        p1 += __shfl_xor_sync(0xffffffffu, p1, 1);
        p1 += __shfl_xor_sync(0xffffffffu, p1, 2);
        if ((lane & 3) == 0) {
            if (r0g < Mvalid)
                atomicAdd(&yout[(long long)b * NL + r0g],
                          p0 * inv[(long long)b * LPAD + r0g]);
            if (r1g < Mvalid)
                atomicAdd(&yout[(long long)b * NL + r1g],
                          p1 * inv[(long long)b * LPAD + r1g]);
        }
    }
}

// ---------------------------------------------------------------------------
// fp32 -> fp16 flat converter; optionally zeroes an aux float array (fused
// zero_sums: first blocks also clear rowsum scratch).
// ---------------------------------------------------------------------------
__global__ __launch_bounds__(256)
void split_hi(const float* __restrict__ src, __half* __restrict__ dhi,
              long long n, float* __restrict__ aux, int naux)
{
    const int gid = blockIdx.x * 256 + threadIdx.x;
    if (aux && gid < naux) aux[gid] = 0.f;
    const long long i = (long long)gid * 4;
    if (i >= n) return;
    float4 v = *(const float4*)(src + i);
    uint2 ph;
    ph.x = pack2h(__float2half_rn(v.x), __float2half_rn(v.y));
    ph.y = pack2h(__float2half_rn(v.z), __float2half_rn(v.w));
    *(uint2*)(dhi + i) = ph;
}

// ---------------------------------------------------------------------------
// inv = 1/sum  AND  y init (y[b,l] = V_b[l]) in one launch
// ---------------------------------------------------------------------------
__global__ __launch_bounds__(256)
void inv_y_kernel(const float* __restrict__ s, float* __restrict__ inv,
                  const float* __restrict__ Vb, float* __restrict__ y)
{
    const int i = blockIdx.x * 256 + threadIdx.x;
    if (i < NB * LPAD) {
        const float v = s[i];
        inv[i] = (v > 0.f) ? (1.f / v) : 0.f;
        const int b = i / LPAD, l = i - b * LPAD;
        if (l < NL) y[b * NL + l] = Vb[l];
    }
}

// ---------------------------------------------------------------------------
extern "C" void kernel_launch(void* const* d_in, const int* in_sizes, int n_in,
                              void* d_out, int out_size)
{
    const float* x  = (const float*)d_in[0];
    const float* Ww = (const float*)d_in[1];
    const float* Wb = (const float*)d_in[2];
    const float* Uw = (const float*)d_in[3];
    const float* Vw = (const float*)d_in[4];
    const float* Vb = (const float*)d_in[5];

    float* y     = (float*)d_out;
    float* alpha = (float*)d_out + (size_t)NB * NL;

    float *sums, *invs;
    __half *xhi, *whi, *zhi, *zThi, *uhi, *ahi;
    cudaGetSymbolAddress((void**)&sums, g_sum);
    cudaGetSymbolAddress((void**)&invs, g_inv);
    cudaGetSymbolAddress((void**)&xhi, g_xhi);
    cudaGetSymbolAddress((void**)&whi, g_Whi);
    cudaGetSymbolAddress((void**)&zhi, g_zhi);
    cudaGetSymbolAddress((void**)&zThi, g_zThi);
    cudaGetSymbolAddress((void**)&uhi, g_Uhi);
    cudaGetSymbolAddress((void**)&ahi, g_ahi);

    cudaFuncSetAttribute((const void*)gemm_mma<false>,
                         cudaFuncAttributeMaxDynamicSharedMemorySize, NSTAGE * STG);
    cudaFuncSetAttribute((const void*)gemm_mma<true>,
                         cudaFuncAttributeMaxDynamicSharedMemorySize, NSTAGE * STG);
    cudaFuncSetAttribute((const void*)gemm_my,
                         cudaFuncAttributeMaxDynamicSharedMemorySize, NSTAGE * STGM);

    // 1) convert x, W, U to fp16 (U launch also zeroes the row-sum scratch)
    {
        long long nx = (long long)NB * NS * NDIN;
        split_hi<<<(unsigned)((nx / 4 + 255) / 256), 256>>>(x, xhi, nx, nullptr, 0);
        long long nw = (long long)NDA * NDIN;
        split_hi<<<(unsigned)((nw / 4 + 255) / 256), 256>>>(Ww, whi, nw, nullptr, 0);
        long long nu = (long long)NL * NDA;
        split_hi<<<(unsigned)((nu / 4 + 255) / 256), 256>>>(Uw, uhi, nu, sums, NB * LPAD);
    }
    // 2) z = tanh(x @ W^T + b) -> fp16 zhi ([b][s][a]) AND zThi ([b][a][s])
    {
        dim3 g(NDA / 128, (NB * NS) / 128, 1);
        gemm_mma<false><<<g, 256, NSTAGE * STG>>>(
            xhi, whi, zhi, zThi, Wb, nullptr,
            NDIN / KCH, NDA, NDIN, NDIN, NDA, 0LL, 0LL, 0LL);
    }
    // 3) e = exp(U @ z^T) -> fp16 g_ahi (pad s-cols forced 0) + row sums
    {
        dim3 g(SPAD / 128, LPAD / 128, NB);
        gemm_mma<true><<<g, 256, NSTAGE * STG>>>(
            uhi, zhi, ahi, nullptr, nullptr, sums,
            NDA / KCH, NS, NDA, NDA, SPAD,
            0LL, (long long)SPAD * NDA, (long long)LPAD * SPAD);
    }
    // 4) inv = 1/sum; y = V_b (one launch)
    inv_y_kernel<<<(NB * LPAD + 255) / 256, 256>>>(sums, invs, Vb, y);

    // 5) fused m/y/alpha: y[b,l] += inv * sum_a (e@z)[b,l,a] * V[l,a];
    //    alpha = e*inv streamed from smem e tiles, balanced across n-tiles.
    {
        dim3 g(NDA / 256, LPAD / 128, NB);
        gemm_my<<<g, 256, NSTAGE * STGM>>>(
            ahi, zThi, Vw, invs, y, alpha,
            63, NL, SPAD, SPAD,
            (long long)LPAD * SPAD, (long long)NDA * SPAD);
    }
}

// round 17
// speedup vs baseline: 1.0137x; 1.0033x over previous
#include <cuda_runtime.h>
#include <cuda_fp16.h>
#include <math.h>
#include <stdint.h>

#define NB 4
#define NS 4000
#define NDIN 1024
#define NDA 512
#define NL 8921
#define SPAD 4096   // padded S
#define LPAD 8960   // padded L (70 * 128)
#define KCH 128     // fp16 K elements per chunk in gemm_mma (2 x 64 sub-bufs)
#define STG 65536   // gemm_mma stage bytes: A 32K (2 subbufs) + B 32K
#define NSTAGE 3
#define KCM 64      // K per chunk in gemm_my
#define STGM 49152  // gemm_my stage bytes: A 16K + B 32K
#define NSTGM 4     // gemm_my pipeline depth (4 x 48K = 192K smem)

// ---------------------------------------------------------------------------
// Scratch (device globals: zero-initialized at module load; padded regions are
// never written so they stay zero -> no bounds checks in GEMM operand loads).
// ---------------------------------------------------------------------------
__device__ __half g_xhi[(size_t)NB * NS * NDIN];    // x hi  [b*s][din]
__device__ __half g_Whi[(size_t)NDA * NDIN];        // W hi  [a][din]
__device__ __half g_zhi[(size_t)NB * SPAD * NDA];   // z hi  [b][s][a]
__device__ __half g_zThi[(size_t)NB * NDA * SPAD];  // z^T hi [b][a][s]
__device__ __half g_Uhi[(size_t)LPAD * NDA];
__device__ __half g_ahi[(size_t)NB * LPAD * SPAD];  // e = exp(score), fp16
__device__ float g_sum[(size_t)NB * LPAD];          // per-row sums of e
__device__ float g_inv[(size_t)NB * LPAD];          // 1 / sums

// ---------------------------------------------------------------------------
// Helpers
// ---------------------------------------------------------------------------
__device__ __forceinline__ uint32_t smem_u32(const void* p) {
    uint32_t a;
    asm("{ .reg .u64 t; cvta.to.shared.u64 t, %1; cvt.u32.u64 %0, t; }"
        : "=r"(a) : "l"(p));
    return a;
}
__device__ __forceinline__ void cpa16(uint32_t dst, const void* src) {
    asm volatile("cp.async.cg.shared.global [%0], [%1], 16;"
                 :: "r"(dst), "l"(src) : "memory");
}
#define CP_COMMIT() asm volatile("cp.async.commit_group;" ::: "memory")
#define CP_WAIT(n)  asm volatile("cp.async.wait_group %0;" :: "n"(n) : "memory")

__device__ __forceinline__ void ldsm4(uint32_t& r0, uint32_t& r1,
                                      uint32_t& r2, uint32_t& r3, uint32_t addr) {
    asm volatile("ldmatrix.sync.aligned.m8n8.x4.shared.b16 {%0,%1,%2,%3}, [%4];"
                 : "=r"(r0), "=r"(r1), "=r"(r2), "=r"(r3) : "r"(addr));
}
__device__ __forceinline__ void mma16816(float* d, const uint32_t* a, const uint32_t* b) {
    asm volatile(
        "mma.sync.aligned.m16n8k16.row.col.f32.f16.f16.f32 "
        "{%0,%1,%2,%3}, {%4,%5,%6,%7}, {%8,%9}, {%0,%1,%2,%3};"
        : "+f"(d[0]), "+f"(d[1]), "+f"(d[2]), "+f"(d[3])
        : "r"(a[0]), "r"(a[1]), "r"(a[2]), "r"(a[3]), "r"(b[0]), "r"(b[1]));
}

__device__ __forceinline__ uint32_t pack2h(__half a, __half b) {
    return (uint32_t)__half_as_ushort(a) | ((uint32_t)__half_as_ushort(b) << 16);
}

// Fast tanh via MUFU.EX2: tanh(v) = 1 - 2/(e^{2v}+1). Rel err ~2^-22,
// fully absorbed by the subsequent fp16 rounding (2^-12).
__device__ __forceinline__ float ftanh(float v) {
    const float e = __expf(2.f * v);
    return 1.f - __fdividef(2.f, e + 1.f);
}

// Swizzled offset inside a (rows x 64) fp16 sub-buffer (128B rows, 8 x 16B
// groups, group ^= row&7 -> conflict-free cp.async + ldmatrix).
__device__ __forceinline__ uint32_t swoff(int row, int c16) {
    return (uint32_t)(row * 128 + ((c16 ^ (row & 7)) * 16));
}

// ---------------------------------------------------------------------------
// fp16 single-pass GEMM, CTA 128x128, 8 warps (2x4), warp tile 64x32,
// K-chunk 128 (2x64 sub-bufs), 3-stage cp.async pipeline.
// EXPSUM=false (z path): Ch(fp16, padded [b][s][a]) = tanh(acc + bias[n]),
//   rows remapped m -> (b,s); ALSO emits the transposed copy Ct ([b][a][s])
//   via an smem tile staged in a dead pipeline stage (coalesced stores).
// EXPSUM=true (scores): Ch(fp16) = exp(acc) for n < Nvalid else 0; atomicAdd
//   per-row partial exp-sums into rowsum (max-free softmax; |logit| < ~6).
// ---------------------------------------------------------------------------
template <bool EXPSUM>
__global__ __launch_bounds__(256, 1)
void gemm_mma(const __half* __restrict__ Ahi, const __half* __restrict__ Bhi,
              __half* __restrict__ Ch, __half* __restrict__ Ct,
              const float* __restrict__ bias, float* __restrict__ rowsum,
              int nk, int Nvalid, int ldA, int ldB, int ldC,
              long long sA, long long sB, long long sC)
{
    extern __shared__ char smem[];
    const uint32_t sb = smem_u32(smem);

    const int t = threadIdx.x, w = t >> 5, lane = t & 31;
    const int m0 = blockIdx.y * 128, n0 = blockIdx.x * 128, b = blockIdx.z;
    const int wm = (w >> 2) * 64, wn = (w & 3) * 32;

    const __half* Ah = Ahi + b * sA + (long long)m0 * ldA;
    const __half* Bh = Bhi + b * sB + (long long)n0 * ldB;

    float acc[4][4][4];
#pragma unroll
    for (int i = 0; i < 4; i++)
#pragma unroll
        for (int j = 0; j < 4; j++)
#pragma unroll
            for (int q = 0; q < 4; q++) acc[i][j][q] = 0.f;

    auto load_stage = [&](int c, int s) {
        const uint32_t st = sb + s * STG;
        const int kb = c * KCH;
#pragma unroll
        for (int j = 0; j < 4; j++) {
            const int cid = t + 256 * j;
            const int row = cid >> 3, c16 = cid & 7;
            const uint32_t sw = swoff(row, c16);
#pragma unroll
            for (int sub = 0; sub < 2; sub++) {
                cpa16(st + sub * 16384 + sw,
                      Ah + (long long)row * ldA + kb + sub * 64 + c16 * 8);
                cpa16(st + 32768 + sub * 16384 + sw,
                      Bh + (long long)row * ldB + kb + sub * 64 + c16 * 8);
            }
        }
    };

    load_stage(0, 0); CP_COMMIT();
    load_stage(1, 1); CP_COMMIT();

    for (int c = 0; c < nk; c++) {
        const int s = c % NSTAGE;
        if (c == nk - 1) { CP_WAIT(0); } else { CP_WAIT(1); }
        __syncthreads();
        if (c + 2 < nk) { load_stage(c + 2, (c + 2) % NSTAGE); CP_COMMIT(); }

        const int rA = lane & 15, chA = lane >> 4;
        const int r8 = ((lane >> 4) << 3) + (lane & 7);
        const int chB = (lane >> 3) & 1;

#pragma unroll
        for (int kk8 = 0; kk8 < 8; kk8++) {
            const int sub = kk8 >> 2, kkl = kk8 & 3;
            const uint32_t stA = sb + s * STG + sub * 16384;
            const uint32_t stB = sb + s * STG + 32768 + sub * 16384;

            uint32_t bh[4][2];
#pragma unroll
            for (int nh = 0; nh < 2; nh++) {
                const uint32_t off = swoff(wn + nh * 16 + r8, kkl * 2 + chB);
                uint32_t r0, r1, r2, r3;
                ldsm4(r0, r1, r2, r3, stB + off);
                bh[nh * 2][0] = r0; bh[nh * 2][1] = r1;
                bh[nh * 2 + 1][0] = r2; bh[nh * 2 + 1][1] = r3;
            }
            uint32_t ah[4][4];
#pragma unroll
            for (int mt = 0; mt < 4; mt++) {
                const uint32_t off = swoff(wm + mt * 16 + rA, kkl * 2 + chA);
                ldsm4(ah[mt][0], ah[mt][1], ah[mt][2], ah[mt][3], stA + off);
            }
#pragma unroll
            for (int mt = 0; mt < 4; mt++)
#pragma unroll
                for (int nt = 0; nt < 4; nt++)
                    mma16816(acc[mt][nt], ah[mt], bh[nt]);
        }
    }

    // Transpose tile lives in a stage not read after the final barrier:
    // only stage (nk-1)%3 is read post-loop, so stage nk%3 is free.
    __half* T = (__half*)(smem + (nk % NSTAGE) * STG);   // T[128][132]

#pragma unroll
    for (int mt = 0; mt < 4; mt++) {
        const int r0g = m0 + wm + mt * 16 + (lane >> 2);
        const int r1g = r0g + 8;
        float p0 = 0.f, p1 = 0.f;

        __half *row0, *row1;
        if (EXPSUM) {
            __half* Cb = Ch + b * sC;
            row0 = Cb + (long long)r0g * ldC;
            row1 = Cb + (long long)r1g * ldC;
        } else {
            // z path: remap m -> (batch, seq) into padded [b][s][a] buffer
            const int b0 = r0g / NS, s0r = r0g - b0 * NS;
            const int b1 = r1g / NS, s1r = r1g - b1 * NS;
            row0 = Ch + ((long long)b0 * SPAD + s0r) * ldC;
            row1 = Ch + ((long long)b1 * SPAD + s1r) * ldC;
        }

#pragma unroll
        for (int nt = 0; nt < 4; nt++) {
            const int cg = n0 + wn + nt * 8 + (lane & 3) * 2;
            if (EXPSUM) {
                const bool ok = (cg < Nvalid);   // 4000 even -> pair-safe
                float e0 = 0.f, e1 = 0.f, e2 = 0.f, e3 = 0.f;
                if (ok) {
                    e0 = __expf(acc[mt][nt][0]); e1 = __expf(acc[mt][nt][1]);
                    e2 = __expf(acc[mt][nt][2]); e3 = __expf(acc[mt][nt][3]);
                }
                *(uint32_t*)(row0 + cg) = pack2h(__float2half_rn(e0), __float2half_rn(e1));
                *(uint32_t*)(row1 + cg) = pack2h(__float2half_rn(e2), __float2half_rn(e3));
                p0 += e0 + e1;
                p1 += e2 + e3;
            } else {
                const float b0v = bias[cg], b1v = bias[cg + 1];
                const __half h00 = __float2half_rn(ftanh(acc[mt][nt][0] + b0v));
                const __half h01 = __float2half_rn(ftanh(acc[mt][nt][1] + b1v));
                const __half h10 = __float2half_rn(ftanh(acc[mt][nt][2] + b0v));
                const __half h11 = __float2half_rn(ftanh(acc[mt][nt][3] + b1v));
                *(uint32_t*)(row0 + cg) = pack2h(h00, h01);
                *(uint32_t*)(row1 + cg) = pack2h(h10, h11);
                // stage into transpose tile: T[a_local][m_local]
                const int cl = cg - n0;
                const int r0l = wm + mt * 16 + (lane >> 2);
                const int r1l = r0l + 8;
                T[(cl + 0) * 132 + r0l] = h00;
                T[(cl + 1) * 132 + r0l] = h01;
                T[(cl + 0) * 132 + r1l] = h10;
                T[(cl + 1) * 132 + r1l] = h11;
            }
        }
        if (EXPSUM) {
            p0 += __shfl_xor_sync(0xffffffffu, p0, 1);
            p0 += __shfl_xor_sync(0xffffffffu, p0, 2);
            p1 += __shfl_xor_sync(0xffffffffu, p1, 1);
            p1 += __shfl_xor_sync(0xffffffffu, p1, 2);
            if ((lane & 3) == 0) {
                atomicAdd(&rowsum[(long long)b * LPAD + r0g], p0);
                atomicAdd(&rowsum[(long long)b * LPAD + r1g], p1);
            }
        }
    }

    if (!EXPSUM) {
        __syncthreads();
        // Coalesced transposed store: zThi[b][a][s]. 4-half groups never
        // straddle a batch boundary (NS % 4 == 0).
#pragma unroll
        for (int it = 0; it < 16; it++) {
            const int i = t + 256 * it;          // 0..4095
            const int al = i >> 5, gsel = i & 31;
            const int mloc = gsel * 4;
            const int m = m0 + mloc;
            const int bb = m / NS, ss = m - bb * NS;
            const __half* p = T + al * 132 + mloc;
            uint2 q;
            q.x = pack2h(p[0], p[1]);
            q.y = pack2h(p[2], p[3]);
            *(uint2*)(Ct + ((long long)bb * NDA + (n0 + al)) * SPAD + ss) = q;
        }
    }
}

// ---------------------------------------------------------------------------
// Fused m+y GEMM: CTA 128(L) x 256(D_A), 8 warps (2x4), warp tile 64x64,
// K-chunk 64, 4-stage cp.async pipeline (prefetch distance 3 -> extra slack
// to cover DRAM latency while the fused alpha store bursts run).
// Reads unnormalized e; y partials scaled by inv_sum[row]. Alpha emission
// (alpha = e*inv, fp32 to d_out) balanced across the two n-tiles by K-chunk.
// ---------------------------------------------------------------------------
__global__ __launch_bounds__(256, 1)
void gemm_my(const __half* __restrict__ Ahi, const __half* __restrict__ Bhi,
             const float* __restrict__ Vw, const float* __restrict__ inv,
             float* __restrict__ yout, float* __restrict__ alpha,
             int nk, int Mvalid, int ldA, int ldB,
             long long sA, long long sB)
{
    extern __shared__ char smem[];
    const uint32_t sb = smem_u32(smem);

    const int t = threadIdx.x, w = t >> 5, lane = t & 31;
    const int m0 = blockIdx.y * 128, n0 = blockIdx.x * 256, b = blockIdx.z;
    const int wm = (w >> 2) * 64, wn = (w & 3) * 64;

    const __half* Ah = Ahi + b * sA + (long long)m0 * ldA;
    const __half* Bh = Bhi + b * sB + (long long)n0 * ldB;

    float acc[4][8][4];
#pragma unroll
    for (int i = 0; i < 4; i++)
#pragma unroll
        for (int j = 0; j < 8; j++)
#pragma unroll
            for (int q = 0; q < 4; q++) acc[i][j][q] = 0.f;

    // stage: A 128x64 @0 (16KB), B 256x64 @16384 (32KB)
    auto load_stage = [&](int c, int s) {
        const uint32_t st = sb + s * STGM;
        const int kb = c * KCM;
#pragma unroll
        for (int j = 0; j < 4; j++) {
            const int cid = t + 256 * j;
            const int row = cid >> 3, c16 = cid & 7;
            cpa16(st + swoff(row, c16), Ah + (long long)row * ldA + kb + c16 * 8);
        }
#pragma unroll
        for (int j = 0; j < 8; j++) {
            const int cid = t + 256 * j;
            const int row = cid >> 3, c16 = cid & 7;
            cpa16(st + 16384 + swoff(row, c16), Bh + (long long)row * ldB + kb + c16 * 8);
        }
    };

    load_stage(0, 0); CP_COMMIT();
    load_stage(1, 1); CP_COMMIT();
    load_stage(2, 2); CP_COMMIT();

    for (int c = 0; c < nk; c++) {
        const int s = c % NSTGM;
        if (c <= nk - 3)       { CP_WAIT(2); }
        else if (c == nk - 2)  { CP_WAIT(1); }
        else                   { CP_WAIT(0); }
        __syncthreads();     // stage s published; stage (c+3)%4 consumed at c-1
        if (c + 3 < nk) { load_stage(c + 3, (c + 3) % NSTGM); CP_COMMIT(); }

        const uint32_t stA = sb + s * STGM;
        const uint32_t stB = stA + 16384;
        const int rA = lane & 15, chA = lane >> 4;
        const int r8 = ((lane >> 4) << 3) + (lane & 7);
        const int chB = (lane >> 3) & 1;

#pragma unroll
        for (int kkl = 0; kkl < 4; kkl++) {
            uint32_t bh[8][2];
#pragma unroll
            for (int nh = 0; nh < 4; nh++) {
                const uint32_t off = swoff(wn + nh * 16 + r8, kkl * 2 + chB);
                uint32_t r0, r1, r2, r3;
                ldsm4(r0, r1, r2, r3, stB + off);
                bh[nh * 2][0] = r0; bh[nh * 2][1] = r1;
                bh[nh * 2 + 1][0] = r2; bh[nh * 2 + 1][1] = r3;
            }
            uint32_t ah[4][4];
#pragma unroll
            for (int mt = 0; mt < 4; mt++) {
                const uint32_t off = swoff(wm + mt * 16 + rA, kkl * 2 + chA);
                ldsm4(ah[mt][0], ah[mt][1], ah[mt][2], ah[mt][3], stA + off);
            }
#pragma unroll
            for (int mt = 0; mt < 4; mt++)
#pragma unroll
                for (int nt = 0; nt < 8; nt++)
                    mma16816(acc[mt][nt], ah[mt], bh[nt]);
        }

        // Fused alpha emission (balanced: each n-tile handles half the chunks)
        if ((c >> 5) == (int)blockIdx.x) {
            const int kb = c * KCM;
#pragma unroll
            for (int j = 0; j < 8; j++) {
                const int g = t + 256 * j;        // 0..2047
                const int row = g >> 4, c4 = g & 15;
                const int col = kb + c4 * 4;      // NS%4==0 -> group all-or-none
                const int lrow = m0 + row;
                if (col < NS && lrow < Mvalid) {
                    const uint32_t addr = stA + swoff(row, c4 >> 1) + (c4 & 1) * 8;
                    uint32_t q0, q1;
                    asm volatile("ld.shared.v2.u32 {%0,%1}, [%2];"
                                 : "=r"(q0), "=r"(q1) : "r"(addr));
                    __half2 h01 = *reinterpret_cast<__half2*>(&q0);
                    __half2 h23 = *reinterpret_cast<__half2*>(&q1);
                    const float iv = inv[(long long)b * LPAD + lrow];
                    float2 f01 = __half22float2(h01), f23 = __half22float2(h23);
                    float4 v = make_float4(f01.x * iv, f01.y * iv,
                                           f23.x * iv, f23.y * iv);
                    *(float4*)(alpha + ((long long)b * NL + lrow) * NS + col) = v;
                }
            }
        }
    }

    // Fused y epilogue: partial dot with Vw rows, scale by inv, atomicAdd.
#pragma unroll
    for (int mt = 0; mt < 4; mt++) {
        const int r0g = m0 + wm + mt * 16 + (lane >> 2);
        const int r1g = r0g + 8;
        float p0 = 0.f, p1 = 0.f;
#pragma unroll
        for (int nt = 0; nt < 8; nt++) {
            const int cg = n0 + wn + nt * 8 + (lane & 3) * 2;
            if (r0g < Mvalid) {
                const float2 vv = *(const float2*)(Vw + (long long)r0g * NDA + cg);
                p0 += acc[mt][nt][0] * vv.x + acc[mt][nt][1] * vv.y;
            }
            if (r1g < Mvalid) {
                const float2 vv = *(const float2*)(Vw + (long long)r1g * NDA + cg);
                p1 += acc[mt][nt][2] * vv.x + acc[mt][nt][3] * vv.y;
            }
        }
        p0 += __shfl_xor_sync(0xffffffffu, p0, 1);
        p0 += __shfl_xor_sync(0xffffffffu, p0, 2);
        p1 += __shfl_xor_sync(0xffffffffu, p1, 1);
        p1 += __shfl_xor_sync(0xffffffffu, p1, 2);
        if ((lane & 3) == 0) {
            if (r0g < Mvalid)
                atomicAdd(&yout[(long long)b * NL + r0g],
                          p0 * inv[(long long)b * LPAD + r0g]);
            if (r1g < Mvalid)
                atomicAdd(&yout[(long long)b * NL + r1g],
                          p1 * inv[(long long)b * LPAD + r1g]);
        }
    }
}

// ---------------------------------------------------------------------------
// fp32 -> fp16 flat converter; optionally zeroes an aux float array (fused
// zero_sums: first blocks also clear rowsum scratch).
// ---------------------------------------------------------------------------
__global__ __launch_bounds__(256)
void split_hi(const float* __restrict__ src, __half* __restrict__ dhi,
              long long n, float* __restrict__ aux, int naux)
{
    const int gid = blockIdx.x * 256 + threadIdx.x;
    if (aux && gid < naux) aux[gid] = 0.f;
    const long long i = (long long)gid * 4;
    if (i >= n) return;
    float4 v = *(const float4*)(src + i);
    uint2 ph;
    ph.x = pack2h(__float2half_rn(v.x), __float2half_rn(v.y));
    ph.y = pack2h(__float2half_rn(v.z), __float2half_rn(v.w));
    *(uint2*)(dhi + i) = ph;
}

// ---------------------------------------------------------------------------
// inv = 1/sum  AND  y init (y[b,l] = V_b[l]) in one launch
// ---------------------------------------------------------------------------
__global__ __launch_bounds__(256)
void inv_y_kernel(const float* __restrict__ s, float* __restrict__ inv,
                  const float* __restrict__ Vb, float* __restrict__ y)
{
    const int i = blockIdx.x * 256 + threadIdx.x;
    if (i < NB * LPAD) {
        const float v = s[i];
        inv[i] = (v > 0.f) ? (1.f / v) : 0.f;
        const int b = i / LPAD, l = i - b * LPAD;
        if (l < NL) y[b * NL + l] = Vb[l];
    }
}

// ---------------------------------------------------------------------------
extern "C" void kernel_launch(void* const* d_in, const int* in_sizes, int n_in,
                              void* d_out, int out_size)
{
    const float* x  = (const float*)d_in[0];
    const float* Ww = (const float*)d_in[1];
    const float* Wb = (const float*)d_in[2];
    const float* Uw = (const float*)d_in[3];
    const float* Vw = (const float*)d_in[4];
    const float* Vb = (const float*)d_in[5];

    float* y     = (float*)d_out;
    float* alpha = (float*)d_out + (size_t)NB * NL;

    float *sums, *invs;
    __half *xhi, *whi, *zhi, *zThi, *uhi, *ahi;
    cudaGetSymbolAddress((void**)&sums, g_sum);
    cudaGetSymbolAddress((void**)&invs, g_inv);
    cudaGetSymbolAddress((void**)&xhi, g_xhi);
    cudaGetSymbolAddress((void**)&whi, g_Whi);
    cudaGetSymbolAddress((void**)&zhi, g_zhi);
    cudaGetSymbolAddress((void**)&zThi, g_zThi);
    cudaGetSymbolAddress((void**)&uhi, g_Uhi);
    cudaGetSymbolAddress((void**)&ahi, g_ahi);

    cudaFuncSetAttribute((const void*)gemm_mma<false>,
                         cudaFuncAttributeMaxDynamicSharedMemorySize, NSTAGE * STG);
    cudaFuncSetAttribute((const void*)gemm_mma<true>,
                         cudaFuncAttributeMaxDynamicSharedMemorySize, NSTAGE * STG);
    cudaFuncSetAttribute((const void*)gemm_my,
                         cudaFuncAttributeMaxDynamicSharedMemorySize, NSTGM * STGM);

    // 1) convert x, W, U to fp16 (U launch also zeroes the row-sum scratch)
    {
        long long nx = (long long)NB * NS * NDIN;
        split_hi<<<(unsigned)((nx / 4 + 255) / 256), 256>>>(x, xhi, nx, nullptr, 0);
        long long nw = (long long)NDA * NDIN;
        split_hi<<<(unsigned)((nw / 4 + 255) / 256), 256>>>(Ww, whi, nw, nullptr, 0);
        long long nu = (long long)NL * NDA;
        split_hi<<<(unsigned)((nu / 4 + 255) / 256), 256>>>(Uw, uhi, nu, sums, NB * LPAD);
    }
    // 2) z = tanh(x @ W^T + b) -> fp16 zhi ([b][s][a]) AND zThi ([b][a][s])
    {
        dim3 g(NDA / 128, (NB * NS) / 128, 1);
        gemm_mma<false><<<g, 256, NSTAGE * STG>>>(
            xhi, whi, zhi, zThi, Wb, nullptr,
            NDIN / KCH, NDA, NDIN, NDIN, NDA, 0LL, 0LL, 0LL);
    }
    // 3) e = exp(U @ z^T) -> fp16 g_ahi (pad s-cols forced 0) + row sums
    {
        dim3 g(SPAD / 128, LPAD / 128, NB);
        gemm_mma<true><<<g, 256, NSTAGE * STG>>>(
            uhi, zhi, ahi, nullptr, nullptr, sums,
            NDA / KCH, NS, NDA, NDA, SPAD,
            0LL, (long long)SPAD * NDA, (long long)LPAD * SPAD);
    }
    // 4) inv = 1/sum; y = V_b (one launch)
    inv_y_kernel<<<(NB * LPAD + 255) / 256, 256>>>(sums, invs, Vb, y);

    // 5) fused m/y/alpha: y[b,l] += inv * sum_a (e@z)[b,l,a] * V[l,a];
    //    alpha = e*inv streamed from smem e tiles, balanced across n-tiles.
    {
        dim3 g(NDA / 256, LPAD / 128, NB);
        gemm_my<<<g, 256, NSTGM * STGM>>>(
            ahi, zThi, Vw, invs, y, alpha,
            63, NL, SPAD, SPAD,
            (long long)LPAD * SPAD, (long long)NDA * SPAD);
    }
}